// round 3
// baseline (speedup 1.0000x reference)
#include <cuda_runtime.h>

#define N_BANDS   224
#define DM        64
#define DS        16
#define N_TILE    4
#define NTHREADS  256
#define LN_EPS    1e-5f

typedef unsigned long long ull;

// ---- row-invariant precomputed state (setup kernel -> main kernel) ----
__device__ ull   g_apack[DM * 8];      // packed decay pairs per d
__device__ float g_coef[DM * 64];      // per d: c2w[16], c1w[16], c2b[16], c1b[16]
__device__ float g_k0w[DM], g_k0b[DM]; // constant terms (incl. D*w_in / D*b_in)
__device__ float g_WoT[DM * DM];       // WoT[k][d] = Wo[d][k]
__device__ int   g_c0;                 // truncation start band

__global__ __launch_bounds__(NTHREADS) void setup_kernel(
    const float* __restrict__ w_in, const float* __restrict__ b_in,
    const float* __restrict__ A_log, const float* __restrict__ Wb,
    const float* __restrict__ Wc, const float* __restrict__ Dvec,
    const float* __restrict__ Wo)
{
    __shared__ float swb[DS], sbb[DS], swc[DS], sbc[DS];
    __shared__ float sa[DM][DS];
    __shared__ float sp0w[DM][DS], sp0b[DM][DS];
    __shared__ float sred[NTHREADS];
    const int tid = threadIdx.x;

    // tiny projections: wb = w_in^T Wb, bb = b_in^T Wb, same for Wc
    if (tid < 64) {
        int s = tid & (DS - 1);
        int which = tid >> 4;
        const float* W = (which < 2) ? Wb : Wc;
        const float* v = (which & 1) ? b_in : w_in;
        float acc = 0.f;
        #pragma unroll 16
        for (int dd = 0; dd < DM; ++dd) acc += v[dd] * W[dd * DS + s];
        if (which == 0)      swb[s] = acc;
        else if (which == 1) sbb[s] = acc;
        else if (which == 2) swc[s] = acc;
        else                 sbc[s] = acc;
    }
    __syncthreads();

    float emin = 1e30f;
    #pragma unroll
    for (int idx = tid; idx < DM * DS; idx += NTHREADS) {
        int d = idx >> 4, s = idx & (DS - 1);
        float e = expf(A_log[idx]);
        emin = fminf(emin, e);
        float a = expf(-e);
        sa[d][s] = a;
        float S0 = (1.0f - __powf(a, (float)N_BANDS)) / (1.0f - a);
        float wd = w_in[d], bd = b_in[d];
        float P2 = wd * swb[s];
        float P1 = wd * sbb[s] + bd * swb[s];
        float P0 = bd * sbb[s] * S0;
        g_coef[d * 64 +      s] = P2 * swc[s];
        g_coef[d * 64 + 16 + s] = P1 * swc[s];
        g_coef[d * 64 + 32 + s] = P2 * sbc[s];
        g_coef[d * 64 + 48 + s] = P1 * sbc[s];
        sp0w[d][s] = P0 * swc[s];
        sp0b[d][s] = P0 * sbc[s];
    }
    sred[tid] = emin;
    __syncthreads();

    if (tid < DM) {
        int d = tid;
        float kw = 0.f, kb = 0.f;
        #pragma unroll
        for (int s = 0; s < DS; ++s) { kw += sp0w[d][s]; kb += sp0b[d][s]; }
        g_k0w[d] = kw + Dvec[d] * w_in[d];
        g_k0b[d] = kb + Dvec[d] * b_in[d];
        #pragma unroll
        for (int i = 0; i < 8; ++i) {
            float2 v = make_float2(sa[d][2 * i], sa[d][2 * i + 1]);
            g_apack[d * 8 + i] = *reinterpret_cast<ull*>(&v);
        }
    }
    // Wo transpose into global
    #pragma unroll
    for (int i = tid; i < DM * DM; i += NTHREADS) {
        int r = i >> 6, k = i & (DM - 1);
        g_WoT[k * DM + r] = Wo[i];
    }
    __syncthreads();
    // block min-reduce of e -> global truncation cutoff
    for (int off = NTHREADS / 2; off > 0; off >>= 1) {
        if (tid < off) sred[tid] = fminf(sred[tid], sred[tid + off]);
        __syncthreads();
    }
    if (tid == 0) {
        // tail rel err <= a_max^K / (1-a_max), a_max = exp(-e_min); K = 20/e_min
        // -> <= ~4e-9, five orders below the 1e-3 threshold. a->1 degrades to full loop.
        int K = (int)ceilf(20.0f / sred[0]);
        if (K > N_BANDS) K = N_BANDS;
        g_c0 = N_BANDS - K;
    }
}

__global__ __launch_bounds__(NTHREADS) void spectral_ssm_kernel(
    const float* __restrict__ x,      // (N, 224)
    const float* __restrict__ bo,     // (64,)
    const float* __restrict__ gamma,  // (64,)
    const float* __restrict__ beta,   // (64,)
    float* __restrict__ out)          // (N, 64)
{
    __shared__ float sh_x[N_TILE][N_BANDS];
    __shared__ float sh_WoT[DM * DM];
    __shared__ float sh_out[N_TILE][DM];
    __shared__ float sh_z[N_TILE][DM];

    const int tid = threadIdx.x;
    const int d   = tid & (DM - 1);
    const int nl  = tid >> 6;
    const int n0  = blockIdx.x * N_TILE;

    // coalesced float4 staging of x tile and pre-transposed Wo
    {
        const float4* xsrc = reinterpret_cast<const float4*>(x + (size_t)n0 * N_BANDS);
        float4* xdst = reinterpret_cast<float4*>(&sh_x[0][0]);
        if (tid < (N_TILE * N_BANDS) / 4) xdst[tid] = xsrc[tid];
        const float4* wsrc = reinterpret_cast<const float4*>(g_WoT);
        float4* wdst = reinterpret_cast<float4*>(sh_WoT);
        #pragma unroll
        for (int i = tid; i < (DM * DM) / 4; i += NTHREADS) wdst[i] = wsrc[i];
    }
    __syncthreads();

    const int c0 = g_c0;

    ull ap[DS / 2], s1p[DS / 2], s2p[DS / 2];
    #pragma unroll
    for (int i = 0; i < DS / 2; ++i) {
        ap[i]  = g_apack[d * 8 + i];
        s1p[i] = 0ULL;
        s2p[i] = 0ULL;
    }

    // ---- truncated Horner loop: S1 = S1*a + x ; S2 = S2*a + x^2 ----
    const float* xr = sh_x[nl];
    #pragma unroll 4
    for (int c = c0; c < N_BANDS; ++c) {
        float xv = xr[c];
        ull xp, xxp;
        asm("mov.b64 %0, {%1, %1};" : "=l"(xp) : "f"(xv));
        asm("mul.rn.f32x2 %0, %1, %2;" : "=l"(xxp) : "l"(xp), "l"(xp));
        #pragma unroll
        for (int i = 0; i < DS / 2; ++i) {
            asm("fma.rn.f32x2 %0, %1, %2, %3;"
                : "=l"(s1p[i]) : "l"(s1p[i]), "l"(ap[i]), "l"(xp));
            asm("fma.rn.f32x2 %0, %1, %2, %3;"
                : "=l"(s2p[i]) : "l"(s2p[i]), "l"(ap[i]), "l"(xxp));
        }
    }

    // ---- unpack ----
    float S1[DS], S2[DS];
    #pragma unroll
    for (int i = 0; i < DS / 2; ++i) {
        asm("mov.b64 {%0, %1}, %2;" : "=f"(S1[2 * i]), "=f"(S1[2 * i + 1]) : "l"(s1p[i]));
        asm("mov.b64 {%0, %1}, %2;" : "=f"(S2[2 * i]), "=f"(S2[2 * i + 1]) : "l"(s2p[i]));
    }

    // ---- epilogue via precomputed coefficients ----
    const float4* cf = reinterpret_cast<const float4*>(g_coef + d * 64);
    float accw = 0.f, accb = 0.f;
    #pragma unroll
    for (int i = 0; i < 4; ++i) {
        float4 t = cf[i];          // c2w
        accw += t.x * S2[4*i] + t.y * S2[4*i+1] + t.z * S2[4*i+2] + t.w * S2[4*i+3];
    }
    #pragma unroll
    for (int i = 0; i < 4; ++i) {
        float4 t = cf[4 + i];      // c1w
        accw += t.x * S1[4*i] + t.y * S1[4*i+1] + t.z * S1[4*i+2] + t.w * S1[4*i+3];
    }
    #pragma unroll
    for (int i = 0; i < 4; ++i) {
        float4 t = cf[8 + i];      // c2b
        accb += t.x * S2[4*i] + t.y * S2[4*i+1] + t.z * S2[4*i+2] + t.w * S2[4*i+3];
    }
    #pragma unroll
    for (int i = 0; i < 4; ++i) {
        float4 t = cf[12 + i];     // c1b
        accb += t.x * S1[4*i] + t.y * S1[4*i+1] + t.z * S1[4*i+2] + t.w * S1[4*i+3];
    }
    const float xlast = xr[N_BANDS - 1];
    float o = xlast * (accw + g_k0w[d]) + (accb + g_k0b[d]);
    sh_out[nl][d] = o;
    __syncthreads();

    // ---- z = out @ Wo^T + bo ----
    float z = bo[d];
    #pragma unroll 16
    for (int k = 0; k < DM; ++k)
        z += sh_out[nl][k] * sh_WoT[k * DM + d];
    sh_z[nl][d] = z;
    __syncthreads();

    // ---- layernorm over d (single pass) ----
    float sum = 0.f, sumsq = 0.f;
    #pragma unroll 16
    for (int k = 0; k < DM; ++k) {
        float v = sh_z[nl][k];
        sum += v;
        sumsq += v * v;
    }
    float mu  = sum * (1.0f / DM);
    float var = sumsq * (1.0f / DM) - mu * mu;
    float r = rsqrtf(var + LN_EPS);

    out[(size_t)(n0 + nl) * DM + d] = gamma[d] * (z - mu) * r + beta[d];
}

extern "C" void kernel_launch(void* const* d_in, const int* in_sizes, int n_in,
                              void* d_out, int out_size) {
    const float* x     = (const float*)d_in[0];
    const float* w_in  = (const float*)d_in[1];
    const float* b_in  = (const float*)d_in[2];
    const float* A_log = (const float*)d_in[3];
    const float* Wb    = (const float*)d_in[4];
    const float* Wc    = (const float*)d_in[5];
    const float* Dv    = (const float*)d_in[6];
    const float* Wo    = (const float*)d_in[7];
    const float* bo    = (const float*)d_in[8];
    const float* gm    = (const float*)d_in[9];
    const float* bt    = (const float*)d_in[10];
    float* out = (float*)d_out;

    int N = in_sizes[0] / N_BANDS;          // 4096
    int grid = N / N_TILE;                  // 1024 blocks

    setup_kernel<<<1, NTHREADS>>>(w_in, b_in, A_log, Wb, Wc, Dv, Wo);
    spectral_ssm_kernel<<<grid, NTHREADS>>>(x, bo, gm, bt, out);
}

// round 4
// speedup vs baseline: 1.0917x; 1.0917x over previous
#include <cuda_runtime.h>

#define N_BANDS   224
#define DM        64
#define DS        16
#define N_TILE    4
#define NTHREADS  256
#define WO_STRIDE 68
#define LN_EPS    1e-5f

typedef unsigned long long ull;

// ---- row-invariant precomputed state (setup kernel -> main kernel) ----
__device__ ull   g_apack[DM * 8];      // packed decay pairs per d
__device__ float g_coef[DM * 64];      // per d: c2w[16], c1w[16], c2b[16], c1b[16]
__device__ float g_k0w[DM], g_k0b[DM]; // constant terms (incl. D*w_in / D*b_in)
__device__ int   g_c0;                 // truncation start band (even)

__global__ __launch_bounds__(NTHREADS) void setup_kernel(
    const float* __restrict__ w_in, const float* __restrict__ b_in,
    const float* __restrict__ A_log, const float* __restrict__ Wb,
    const float* __restrict__ Wc, const float* __restrict__ Dvec)
{
    __shared__ float swb[DS], sbb[DS], swc[DS], sbc[DS];
    __shared__ unsigned s_emin[NTHREADS / 32];
    const int tid = threadIdx.x;

    // tiny projections: wb = w_in^T Wb, bb = b_in^T Wb, same for Wc
    if (tid < 64) {
        int s = tid & (DS - 1);
        int which = tid >> 4;
        const float* W = (which < 2) ? Wb : Wc;
        const float* v = (which & 1) ? b_in : w_in;
        float acc = 0.f;
        #pragma unroll 16
        for (int dd = 0; dd < DM; ++dd) acc += v[dd] * W[dd * DS + s];
        if (which == 0)      swb[s] = acc;
        else if (which == 1) sbb[s] = acc;
        else if (which == 2) swc[s] = acc;
        else                 sbc[s] = acc;
    }
    __syncthreads();

    // thread handles (d, s0..s0+3):  d = tid/4, s0 = (tid%4)*4
    const int d  = tid >> 2;
    const int s0 = (tid & 3) * 4;
    const float wd = w_in[d], bd = b_in[d];

    float a[4];
    float emin = 1e30f;
    float kw = 0.f, kb = 0.f;
    #pragma unroll
    for (int j = 0; j < 4; ++j) {
        int s = s0 + j;
        float e = expf(A_log[d * DS + s]);
        emin = fminf(emin, e);
        float av = expf(-e);
        a[j] = av;
        float S0 = (1.0f - __powf(av, (float)N_BANDS)) / (1.0f - av);
        float P2 = wd * swb[s];
        float P1 = wd * sbb[s] + bd * swb[s];
        float P0 = bd * sbb[s] * S0;
        g_coef[d * 64 +      s] = P2 * swc[s];
        g_coef[d * 64 + 16 + s] = P1 * swc[s];
        g_coef[d * 64 + 32 + s] = P2 * sbc[s];
        g_coef[d * 64 + 48 + s] = P1 * sbc[s];
        kw += P0 * swc[s];
        kb += P0 * sbc[s];
    }
    // packed decay pairs (contiguous s block -> direct pack, no smem)
    {
        float2 v0 = make_float2(a[0], a[1]);
        float2 v1 = make_float2(a[2], a[3]);
        g_apack[d * 8 + s0 / 2]     = *reinterpret_cast<ull*>(&v0);
        g_apack[d * 8 + s0 / 2 + 1] = *reinterpret_cast<ull*>(&v1);
    }
    // combine k0 over the 4 threads of this d (contiguous lanes in one warp)
    kw += __shfl_xor_sync(0xffffffffu, kw, 1);
    kw += __shfl_xor_sync(0xffffffffu, kw, 2);
    kb += __shfl_xor_sync(0xffffffffu, kb, 1);
    kb += __shfl_xor_sync(0xffffffffu, kb, 2);
    if ((tid & 3) == 0) {
        g_k0w[d] = kw + Dvec[d] * wd;
        g_k0b[d] = kb + Dvec[d] * bd;
    }
    // global min of e (positive floats: bit pattern is order-preserving)
    unsigned em = __reduce_min_sync(0xffffffffu, __float_as_uint(emin));
    if ((tid & 31) == 0) s_emin[tid >> 5] = em;
    __syncthreads();
    if (tid == 0) {
        unsigned m = s_emin[0];
        #pragma unroll
        for (int i = 1; i < NTHREADS / 32; ++i) m = min(m, s_emin[i]);
        float e_min = __uint_as_float(m);
        // tail rel err <= exp(-16)/(1-a_max) ~ 4e-7; a->1 degrades to full loop
        int K = (int)ceilf(16.0f / e_min);
        K = (K + 1) & ~1;                 // even
        if (K > N_BANDS) K = N_BANDS;
        g_c0 = N_BANDS - K;
    }
}

__global__ __launch_bounds__(NTHREADS) void spectral_ssm_kernel(
    const float* __restrict__ x,      // (N, 224)
    const float* __restrict__ Wo,     // (64,64) row-major (out,in)
    const float* __restrict__ bo,     // (64,)
    const float* __restrict__ gamma,  // (64,)
    const float* __restrict__ beta,   // (64,)
    float* __restrict__ out)          // (N, 64)
{
    __shared__ float sh_x[N_TILE][N_BANDS];
    __shared__ float sh_Wo[DM * WO_STRIDE];   // row d at d*68, conflict-free LDS.128
    __shared__ float sh_out[N_TILE][DM];
    __shared__ float2 sh_part[NTHREADS / 32];

    const int tid = threadIdx.x;
    const int d   = tid & (DM - 1);
    const int nl  = tid >> 6;
    const int n0  = blockIdx.x * N_TILE;

    // coalesced float4 staging
    {
        const float4* xsrc = reinterpret_cast<const float4*>(x + (size_t)n0 * N_BANDS);
        float4* xdst = reinterpret_cast<float4*>(&sh_x[0][0]);
        if (tid < (N_TILE * N_BANDS) / 4) xdst[tid] = xsrc[tid];
        const float4* wsrc = reinterpret_cast<const float4*>(Wo);
        #pragma unroll
        for (int i = tid; i < (DM * DM) / 4; i += NTHREADS) {
            int r = i >> 4, c = i & 15;
            *reinterpret_cast<float4*>(&sh_Wo[r * WO_STRIDE + c * 4]) = wsrc[i];
        }
    }
    __syncthreads();

    const int c0 = g_c0;

    ull ap[DS / 2], s1p[DS / 2], s2p[DS / 2];
    #pragma unroll
    for (int i = 0; i < DS / 2; ++i) {
        ap[i]  = g_apack[d * 8 + i];
        s1p[i] = 0ULL;
        s2p[i] = 0ULL;
    }

    // ---- truncated Horner loop, 2 bands per iteration ----
    const float* xr = sh_x[nl];
    #pragma unroll 2
    for (int c = c0; c < N_BANDS; c += 2) {
        float2 xv = *reinterpret_cast<const float2*>(xr + c);
        ull xp0, xp1, xx0, xx1;
        asm("mov.b64 %0, {%1, %1};" : "=l"(xp0) : "f"(xv.x));
        asm("mov.b64 %0, {%1, %1};" : "=l"(xp1) : "f"(xv.y));
        asm("mul.rn.f32x2 %0, %1, %2;" : "=l"(xx0) : "l"(xp0), "l"(xp0));
        asm("mul.rn.f32x2 %0, %1, %2;" : "=l"(xx1) : "l"(xp1), "l"(xp1));
        #pragma unroll
        for (int i = 0; i < DS / 2; ++i) {
            asm("fma.rn.f32x2 %0, %1, %2, %3;"
                : "=l"(s1p[i]) : "l"(s1p[i]), "l"(ap[i]), "l"(xp0));
            asm("fma.rn.f32x2 %0, %1, %2, %3;"
                : "=l"(s2p[i]) : "l"(s2p[i]), "l"(ap[i]), "l"(xx0));
        }
        #pragma unroll
        for (int i = 0; i < DS / 2; ++i) {
            asm("fma.rn.f32x2 %0, %1, %2, %3;"
                : "=l"(s1p[i]) : "l"(s1p[i]), "l"(ap[i]), "l"(xp1));
            asm("fma.rn.f32x2 %0, %1, %2, %3;"
                : "=l"(s2p[i]) : "l"(s2p[i]), "l"(ap[i]), "l"(xx1));
        }
    }

    // ---- unpack ----
    float S1[DS], S2[DS];
    #pragma unroll
    for (int i = 0; i < DS / 2; ++i) {
        asm("mov.b64 {%0, %1}, %2;" : "=f"(S1[2 * i]), "=f"(S1[2 * i + 1]) : "l"(s1p[i]));
        asm("mov.b64 {%0, %1}, %2;" : "=f"(S2[2 * i]), "=f"(S2[2 * i + 1]) : "l"(s2p[i]));
    }

    // ---- epilogue via precomputed coefficients ----
    const float4* cf = reinterpret_cast<const float4*>(g_coef + d * 64);
    float accw = 0.f, accb = 0.f;
    #pragma unroll
    for (int i = 0; i < 4; ++i) {
        float4 t = cf[i];          // c2w
        accw += t.x * S2[4*i] + t.y * S2[4*i+1] + t.z * S2[4*i+2] + t.w * S2[4*i+3];
    }
    #pragma unroll
    for (int i = 0; i < 4; ++i) {
        float4 t = cf[4 + i];      // c1w
        accw += t.x * S1[4*i] + t.y * S1[4*i+1] + t.z * S1[4*i+2] + t.w * S1[4*i+3];
    }
    #pragma unroll
    for (int i = 0; i < 4; ++i) {
        float4 t = cf[8 + i];      // c2b
        accb += t.x * S2[4*i] + t.y * S2[4*i+1] + t.z * S2[4*i+2] + t.w * S2[4*i+3];
    }
    #pragma unroll
    for (int i = 0; i < 4; ++i) {
        float4 t = cf[12 + i];     // c1b
        accb += t.x * S1[4*i] + t.y * S1[4*i+1] + t.z * S1[4*i+2] + t.w * S1[4*i+3];
    }
    const float xlast = xr[N_BANDS - 1];
    float o = xlast * (accw + g_k0w[d]) + (accb + g_k0b[d]);
    sh_out[nl][d] = o;
    __syncthreads();

    // ---- z = out @ Wo^T + bo : thread d dots its contiguous Wo row ----
    float z = bo[d];
    {
        const float4* wrow = reinterpret_cast<const float4*>(sh_Wo + d * WO_STRIDE);
        const float4* orow = reinterpret_cast<const float4*>(&sh_out[nl][0]);
        #pragma unroll
        for (int i = 0; i < DM / 4; ++i) {
            float4 w = wrow[i];
            float4 o4 = orow[i];
            z += o4.x * w.x + o4.y * w.y + o4.z * w.z + o4.w * w.w;
        }
    }

    // ---- layernorm: shuffle-reduce over the 64-thread row group (2 warps) ----
    float sum = z, sq = z * z;
    #pragma unroll
    for (int off = 16; off > 0; off >>= 1) {
        sum += __shfl_xor_sync(0xffffffffu, sum, off);
        sq  += __shfl_xor_sync(0xffffffffu, sq,  off);
    }
    if ((tid & 31) == 0) sh_part[tid >> 5] = make_float2(sum, sq);
    __syncthreads();
    float2 p0 = sh_part[nl * 2], p1 = sh_part[nl * 2 + 1];
    float mu  = (p0.x + p1.x) * (1.0f / DM);
    float var = (p0.y + p1.y) * (1.0f / DM) - mu * mu;
    float r = rsqrtf(var + LN_EPS);

    out[(size_t)(n0 + nl) * DM + d] = gamma[d] * (z - mu) * r + beta[d];
}

extern "C" void kernel_launch(void* const* d_in, const int* in_sizes, int n_in,
                              void* d_out, int out_size) {
    const float* x     = (const float*)d_in[0];
    const float* w_in  = (const float*)d_in[1];
    const float* b_in  = (const float*)d_in[2];
    const float* A_log = (const float*)d_in[3];
    const float* Wb    = (const float*)d_in[4];
    const float* Wc    = (const float*)d_in[5];
    const float* Dv    = (const float*)d_in[6];
    const float* Wo    = (const float*)d_in[7];
    const float* bo    = (const float*)d_in[8];
    const float* gm    = (const float*)d_in[9];
    const float* bt    = (const float*)d_in[10];
    float* out = (float*)d_out;

    int N = in_sizes[0] / N_BANDS;          // 4096
    int grid = N / N_TILE;                  // 1024 blocks

    setup_kernel<<<1, NTHREADS>>>(w_in, b_in, A_log, Wb, Wc, Dv);
    spectral_ssm_kernel<<<grid, NTHREADS>>>(x, Wo, bo, gm, bt, out);
}

// round 5
// speedup vs baseline: 1.7559x; 1.6084x over previous
#include <cuda_runtime.h>

#define N_BANDS   224
#define DM        64
#define DS        16
#define RT        16      // rows per block
#define RPT       4       // rows per thread (RT / 4 groups)
#define NTHREADS  256
#define CSTRIDE   68      // coef row stride (floats), conflict-free LDS.128
#define ASTRIDE   9       // decay row stride (ull)
#define LN_EPS    1e-5f

typedef unsigned long long ull;

__global__ __launch_bounds__(NTHREADS, 2) void spectral_fused_kernel(
    const float* __restrict__ x,      // (N, 224)
    const float* __restrict__ w_in,   // (64,)
    const float* __restrict__ b_in,   // (64,)
    const float* __restrict__ A_log,  // (64,16)
    const float* __restrict__ Wb,     // (64,16)
    const float* __restrict__ Wc,     // (64,16)
    const float* __restrict__ Dvec,   // (64,)
    const float* __restrict__ Wo,     // (64,64) row-major (out,in)
    const float* __restrict__ bo,     // (64,)
    const float* __restrict__ gamma,  // (64,)
    const float* __restrict__ beta,   // (64,)
    float* __restrict__ out)          // (N, 64)
{
    __shared__ float sh_x[RT][N_BANDS];          // 14336 B
    __shared__ float sh_coef[DM * CSTRIDE];      // 17408 B
    __shared__ ull   sh_ap[DM * ASTRIDE];        //  4608 B
    __shared__ float sh_out[RT][DM];             //  4096 B
    __shared__ float sh_proj[4][DS];             // wb, bb, wc, bc
    __shared__ float sh_k0w[DM], sh_k0b[DM];
    __shared__ unsigned sh_emin[NTHREADS / 32];
    __shared__ float2 sh_part[RT][2];

    const int tid = threadIdx.x;
    const int d   = tid & (DM - 1);
    const int nl  = tid >> 6;
    const int n0  = blockIdx.x * RT;

    // hoist per-d epilogue constants early (hide LDG latency behind setup)
    const float bod = bo[d], gd = gamma[d], btd = beta[d];

    // ---- phase 1a: stage x tile (coalesced float4) ----
    {
        const float4* xsrc = reinterpret_cast<const float4*>(x + (size_t)n0 * N_BANDS);
        float4* xdst = reinterpret_cast<float4*>(&sh_x[0][0]);
        #pragma unroll
        for (int i = tid; i < RT * N_BANDS / 4; i += NTHREADS) xdst[i] = xsrc[i];
    }
    // ---- phase 1b: projections wb = w_in^T Wb etc., 4-way split per (s,which) ----
    {
        const int pair = tid >> 2, piece = tid & 3;
        const int s = pair & (DS - 1), which = pair >> 4;
        const float* W = (which < 2) ? Wb : Wc;
        const float* v = (which & 1) ? b_in : w_in;
        const int dd0 = piece * 16;
        float acc = 0.f;
        #pragma unroll 16
        for (int j = 0; j < 16; ++j) acc += v[dd0 + j] * W[(dd0 + j) * DS + s];
        acc += __shfl_xor_sync(0xffffffffu, acc, 1);
        acc += __shfl_xor_sync(0xffffffffu, acc, 2);
        if (piece == 0) sh_proj[which][s] = acc;
    }
    __syncthreads();

    // ---- phase 2: decays + coefficient algebra (thread handles d2 = tid/4, 4 s values) ----
    {
        const int d2 = tid >> 2, s0 = (tid & 3) * 4;
        const float wd = w_in[d2], bd = b_in[d2];
        float emin = 1e30f, kw = 0.f, kb = 0.f;
        float a0 = 0.f, a1 = 0.f, a2v = 0.f, a3 = 0.f;
        #pragma unroll
        for (int j = 0; j < 4; ++j) {
            int s = s0 + j;
            float e = expf(A_log[d2 * DS + s]);
            emin = fminf(emin, e);
            float av = expf(-e);
            if (j == 0) a0 = av; else if (j == 1) a1 = av;
            else if (j == 2) a2v = av; else a3 = av;
            float S0 = (1.0f - __powf(av, (float)N_BANDS)) / (1.0f - av);
            float swb = sh_proj[0][s], sbb = sh_proj[1][s];
            float swc = sh_proj[2][s], sbc = sh_proj[3][s];
            float P2 = wd * swb;
            float P1 = wd * sbb + bd * swb;
            float P0 = bd * sbb * S0;
            sh_coef[d2 * CSTRIDE +      s] = P2 * swc;
            sh_coef[d2 * CSTRIDE + 16 + s] = P1 * swc;
            sh_coef[d2 * CSTRIDE + 32 + s] = P2 * sbc;
            sh_coef[d2 * CSTRIDE + 48 + s] = P1 * sbc;
            kw += P0 * swc;
            kb += P0 * sbc;
        }
        {
            float2 v0 = make_float2(a0, a1);
            float2 v1 = make_float2(a2v, a3);
            sh_ap[d2 * ASTRIDE + (s0 >> 1)]     = *reinterpret_cast<ull*>(&v0);
            sh_ap[d2 * ASTRIDE + (s0 >> 1) + 1] = *reinterpret_cast<ull*>(&v1);
        }
        kw += __shfl_xor_sync(0xffffffffu, kw, 1);
        kw += __shfl_xor_sync(0xffffffffu, kw, 2);
        kb += __shfl_xor_sync(0xffffffffu, kb, 1);
        kb += __shfl_xor_sync(0xffffffffu, kb, 2);
        if ((tid & 3) == 0) {
            sh_k0w[d2] = kw + Dvec[d2] * wd;
            sh_k0b[d2] = kb + Dvec[d2] * bd;
        }
        unsigned em = __reduce_min_sync(0xffffffffu, __float_as_uint(emin));
        if ((tid & 31) == 0) sh_emin[tid >> 5] = em;
    }
    __syncthreads();

    // ---- truncation cutoff (every thread, deterministic) ----
    // tail rel err <= exp(-16)/(1-a_max) ~ 4e-7; a->1 degrades to full loop
    int c0;
    {
        unsigned m = sh_emin[0];
        #pragma unroll
        for (int i = 1; i < NTHREADS / 32; ++i) m = min(m, sh_emin[i]);
        float e_min = __uint_as_float(m);
        int K = (int)ceilf(16.0f / e_min);
        K = (K + 1) & ~1;
        if (K > N_BANDS) K = N_BANDS;
        c0 = N_BANDS - K;
    }

    // ---- load packed decays for this thread's d ----
    ull ap[DS / 2];
    #pragma unroll
    for (int i = 0; i < DS / 2; ++i) ap[i] = sh_ap[d * ASTRIDE + i];

    const float4* cf = reinterpret_cast<const float4*>(sh_coef + d * CSTRIDE);
    const float k0w = sh_k0w[d], k0b = sh_k0b[d];

    // ---- phase 3: per-row Horner scan + coefficient epilogue (RPT rows sequentially) ----
    float o[RPT];
    #pragma unroll
    for (int r = 0; r < RPT; ++r) {
        const int row = nl * RPT + r;
        const float* xr = sh_x[row];

        ull s1p[DS / 2], s2p[DS / 2];
        #pragma unroll
        for (int i = 0; i < DS / 2; ++i) { s1p[i] = 0ULL; s2p[i] = 0ULL; }

        #pragma unroll 2
        for (int c = c0; c < N_BANDS; c += 2) {
            float2 xv = *reinterpret_cast<const float2*>(xr + c);
            ull xp0, xp1, xx0, xx1;
            asm("mov.b64 %0, {%1, %1};" : "=l"(xp0) : "f"(xv.x));
            asm("mov.b64 %0, {%1, %1};" : "=l"(xp1) : "f"(xv.y));
            asm("mul.rn.f32x2 %0, %1, %2;" : "=l"(xx0) : "l"(xp0), "l"(xp0));
            asm("mul.rn.f32x2 %0, %1, %2;" : "=l"(xx1) : "l"(xp1), "l"(xp1));
            #pragma unroll
            for (int i = 0; i < DS / 2; ++i) {
                asm("fma.rn.f32x2 %0, %1, %2, %3;"
                    : "=l"(s1p[i]) : "l"(s1p[i]), "l"(ap[i]), "l"(xp0));
                asm("fma.rn.f32x2 %0, %1, %2, %3;"
                    : "=l"(s2p[i]) : "l"(s2p[i]), "l"(ap[i]), "l"(xx0));
            }
            #pragma unroll
            for (int i = 0; i < DS / 2; ++i) {
                asm("fma.rn.f32x2 %0, %1, %2, %3;"
                    : "=l"(s1p[i]) : "l"(s1p[i]), "l"(ap[i]), "l"(xp1));
                asm("fma.rn.f32x2 %0, %1, %2, %3;"
                    : "=l"(s2p[i]) : "l"(s2p[i]), "l"(ap[i]), "l"(xx1));
            }
        }

        float S1[DS], S2[DS];
        #pragma unroll
        for (int i = 0; i < DS / 2; ++i) {
            asm("mov.b64 {%0, %1}, %2;" : "=f"(S1[2*i]), "=f"(S1[2*i+1]) : "l"(s1p[i]));
            asm("mov.b64 {%0, %1}, %2;" : "=f"(S2[2*i]), "=f"(S2[2*i+1]) : "l"(s2p[i]));
        }

        float accw = 0.f, accb = 0.f;
        #pragma unroll
        for (int i = 0; i < 4; ++i) {
            float4 t = cf[i];
            accw += t.x * S2[4*i] + t.y * S2[4*i+1] + t.z * S2[4*i+2] + t.w * S2[4*i+3];
        }
        #pragma unroll
        for (int i = 0; i < 4; ++i) {
            float4 t = cf[4 + i];
            accw += t.x * S1[4*i] + t.y * S1[4*i+1] + t.z * S1[4*i+2] + t.w * S1[4*i+3];
        }
        #pragma unroll
        for (int i = 0; i < 4; ++i) {
            float4 t = cf[8 + i];
            accb += t.x * S2[4*i] + t.y * S2[4*i+1] + t.z * S2[4*i+2] + t.w * S2[4*i+3];
        }
        #pragma unroll
        for (int i = 0; i < 4; ++i) {
            float4 t = cf[12 + i];
            accb += t.x * S1[4*i] + t.y * S1[4*i+1] + t.z * S1[4*i+2] + t.w * S1[4*i+3];
        }
        const float xlast = xr[N_BANDS - 1];
        o[r] = xlast * (accw + k0w) + (accb + k0b);
    }
    #pragma unroll
    for (int r = 0; r < RPT; ++r) sh_out[nl * RPT + r][d] = o[r];
    __syncthreads();

    // ---- phase 4: out-proj (Wo row d from gmem, L1-resident) + layernorm ----
    const float4* wrow = reinterpret_cast<const float4*>(Wo + d * DM);
    float z[RPT];
    #pragma unroll
    for (int r = 0; r < RPT; ++r) {
        const int row = nl * RPT + r;
        const float4* orow = reinterpret_cast<const float4*>(&sh_out[row][0]);
        float zz = bod;
        #pragma unroll
        for (int i = 0; i < DM / 4; ++i) {
            float4 w = wrow[i];
            float4 o4 = orow[i];
            zz += o4.x * w.x + o4.y * w.y + o4.z * w.z + o4.w * w.w;
        }
        z[r] = zz;
        float sum = zz, sq = zz * zz;
        #pragma unroll
        for (int off = 16; off > 0; off >>= 1) {
            sum += __shfl_xor_sync(0xffffffffu, sum, off);
            sq  += __shfl_xor_sync(0xffffffffu, sq,  off);
        }
        if ((tid & 31) == 0) sh_part[row][(tid >> 5) & 1] = make_float2(sum, sq);
    }
    __syncthreads();

    #pragma unroll
    for (int r = 0; r < RPT; ++r) {
        const int row = nl * RPT + r;
        float2 p0 = sh_part[row][0], p1 = sh_part[row][1];
        float mu  = (p0.x + p1.x) * (1.0f / DM);
        float var = (p0.y + p1.y) * (1.0f / DM) - mu * mu;
        float rn = rsqrtf(var + LN_EPS);
        out[(size_t)(n0 + row) * DM + d] = gd * (z[r] - mu) * rn + btd;
    }
}

extern "C" void kernel_launch(void* const* d_in, const int* in_sizes, int n_in,
                              void* d_out, int out_size) {
    const float* x     = (const float*)d_in[0];
    const float* w_in  = (const float*)d_in[1];
    const float* b_in  = (const float*)d_in[2];
    const float* A_log = (const float*)d_in[3];
    const float* Wb    = (const float*)d_in[4];
    const float* Wc    = (const float*)d_in[5];
    const float* Dv    = (const float*)d_in[6];
    const float* Wo    = (const float*)d_in[7];
    const float* bo    = (const float*)d_in[8];
    const float* gm    = (const float*)d_in[9];
    const float* bt    = (const float*)d_in[10];
    float* out = (float*)d_out;

    int N = in_sizes[0] / N_BANDS;          // 4096
    int grid = N / RT;                      // 256 blocks
    spectral_fused_kernel<<<grid, NTHREADS>>>(x, w_in, b_in, A_log, Wb, Wc, Dv,
                                              Wo, bo, gm, bt, out);
}

// round 6
// speedup vs baseline: 1.9635x; 1.1182x over previous
#include <cuda_runtime.h>

#define N_BANDS   224
#define DM        64
#define DS        16
#define MAXROWS   14      // max rows per block (grid = 2*148, 4096/296 -> 13..14)
#define NTHREADS  256
#define NGROUPS   4       // 256/64
#define CSTRIDE   68      // coef row stride (floats), conflict-free LDS.128
#define ASTRIDE   9       // decay row stride (ull)
#define LN_EPS    1e-5f

typedef unsigned long long ull;

__global__ __launch_bounds__(NTHREADS, 2) void spectral_fused_kernel(
    const float* __restrict__ x,      // (N, 224)
    const float* __restrict__ w_in,   // (64,)
    const float* __restrict__ b_in,   // (64,)
    const float* __restrict__ A_log,  // (64,16)
    const float* __restrict__ Wb,     // (64,16)
    const float* __restrict__ Wc,     // (64,16)
    const float* __restrict__ Dvec,   // (64,)
    const float* __restrict__ Wo,     // (64,64) row-major (out,in)
    const float* __restrict__ bo,     // (64,)
    const float* __restrict__ gamma,  // (64,)
    const float* __restrict__ beta,   // (64,)
    float* __restrict__ out,          // (N, 64)
    int n_total)
{
    __shared__ float sh_x[MAXROWS][N_BANDS];     // 12544 B
    __shared__ float sh_coef[DM * CSTRIDE];      // 17408 B
    __shared__ ull   sh_ap[DM * ASTRIDE];        //  4608 B
    __shared__ float sh_out[MAXROWS][DM];        //  3584 B
    __shared__ float sh_proj[4][DS];
    __shared__ float sh_k0w[DM], sh_k0b[DM];
    __shared__ unsigned sh_emin[NTHREADS / 32];
    __shared__ float2 sh_part[MAXROWS][2];

    const int tid = threadIdx.x;
    const int d   = tid & (DM - 1);
    const int nl  = tid >> 6;

    // balanced row partition over gridDim.x blocks
    const int row0  = (int)(((long long)blockIdx.x * n_total) / gridDim.x);
    const int row1  = (int)(((long long)(blockIdx.x + 1) * n_total) / gridDim.x);
    const int nrows = row1 - row0;

    const float bod = bo[d], gd = gamma[d], btd = beta[d];

    // ---- phase 1a: stage x tile (coalesced float4) ----
    {
        const float4* xsrc = reinterpret_cast<const float4*>(x + (size_t)row0 * N_BANDS);
        float4* xdst = reinterpret_cast<float4*>(&sh_x[0][0]);
        const int nvec = nrows * (N_BANDS / 4);
        for (int i = tid; i < nvec; i += NTHREADS) xdst[i] = xsrc[i];
    }
    // ---- phase 1b: projections wb = w_in^T Wb etc. (64 pairs x 4 pieces) ----
    {
        const int pair = tid >> 2, piece = tid & 3;
        const int s = pair & (DS - 1), which = pair >> 4;
        const float* W = (which < 2) ? Wb : Wc;
        const float* v = (which & 1) ? b_in : w_in;
        const int dd0 = piece * 16;
        float acc = 0.f;
        #pragma unroll 16
        for (int j = 0; j < 16; ++j) acc += v[dd0 + j] * W[(dd0 + j) * DS + s];
        acc += __shfl_xor_sync(0xffffffffu, acc, 1);
        acc += __shfl_xor_sync(0xffffffffu, acc, 2);
        if (piece == 0) sh_proj[which][s] = acc;
    }
    __syncthreads();

    // ---- phase 2: decays + coefficient algebra (thread: d2 = tid/4, 4 s-values) ----
    {
        const int d2 = tid >> 2, s0 = (tid & 3) * 4;
        const float wd = w_in[d2], bd = b_in[d2];
        float emin = 1e30f, kw = 0.f, kb = 0.f;
        float a0 = 0.f, a1 = 0.f, a2v = 0.f, a3 = 0.f;
        #pragma unroll
        for (int j = 0; j < 4; ++j) {
            int s = s0 + j;
            float e = expf(A_log[d2 * DS + s]);
            emin = fminf(emin, e);
            float av = expf(-e);
            if (j == 0) a0 = av; else if (j == 1) a1 = av;
            else if (j == 2) a2v = av; else a3 = av;
            float S0 = (1.0f - __powf(av, (float)N_BANDS)) / (1.0f - av);
            float swb = sh_proj[0][s], sbb = sh_proj[1][s];
            float swc = sh_proj[2][s], sbc = sh_proj[3][s];
            float P2 = wd * swb;
            float P1 = wd * sbb + bd * swb;
            float P0 = bd * sbb * S0;
            sh_coef[d2 * CSTRIDE +      s] = P2 * swc;
            sh_coef[d2 * CSTRIDE + 16 + s] = P1 * swc;
            sh_coef[d2 * CSTRIDE + 32 + s] = P2 * sbc;
            sh_coef[d2 * CSTRIDE + 48 + s] = P1 * sbc;
            kw += P0 * swc;
            kb += P0 * sbc;
        }
        {
            float2 v0 = make_float2(a0, a1);
            float2 v1 = make_float2(a2v, a3);
            sh_ap[d2 * ASTRIDE + (s0 >> 1)]     = *reinterpret_cast<ull*>(&v0);
            sh_ap[d2 * ASTRIDE + (s0 >> 1) + 1] = *reinterpret_cast<ull*>(&v1);
        }
        kw += __shfl_xor_sync(0xffffffffu, kw, 1);
        kw += __shfl_xor_sync(0xffffffffu, kw, 2);
        kb += __shfl_xor_sync(0xffffffffu, kb, 1);
        kb += __shfl_xor_sync(0xffffffffu, kb, 2);
        if ((tid & 3) == 0) {
            sh_k0w[d2] = kw + Dvec[d2] * wd;
            sh_k0b[d2] = kb + Dvec[d2] * bd;
        }
        unsigned em = __reduce_min_sync(0xffffffffu, __float_as_uint(emin));
        if ((tid & 31) == 0) sh_emin[tid >> 5] = em;
    }
    __syncthreads();

    // ---- truncation cutoff ----
    // tail rel err <= exp(-12)/(1-a_max) ~ 1.2e-5; a->1 degrades to full loop
    int c0;
    {
        unsigned m = sh_emin[0];
        #pragma unroll
        for (int i = 1; i < NTHREADS / 32; ++i) m = min(m, sh_emin[i]);
        float e_min = __uint_as_float(m);
        int K = (int)ceilf(12.0f / e_min);
        K = (K + 1) & ~1;
        if (K > N_BANDS) K = N_BANDS;
        c0 = N_BANDS - K;
    }

    ull ap[DS / 2];
    #pragma unroll
    for (int i = 0; i < DS / 2; ++i) ap[i] = sh_ap[d * ASTRIDE + i];

    const float4* cf = reinterpret_cast<const float4*>(sh_coef + d * CSTRIDE);
    const float k0w = sh_k0w[d], k0b = sh_k0b[d];

    // ---- phase 3: per-row Horner scan + coefficient epilogue ----
    // ONE row live at a time (unroll 1) => single accumulator set, no spills.
    #pragma unroll 1
    for (int row = nl; row < nrows; row += NGROUPS) {
        const float* xr = sh_x[row];

        ull s1p[DS / 2], s2p[DS / 2];
        #pragma unroll
        for (int i = 0; i < DS / 2; ++i) { s1p[i] = 0ULL; s2p[i] = 0ULL; }

        #pragma unroll 2
        for (int c = c0; c < N_BANDS; c += 2) {
            float2 xv = *reinterpret_cast<const float2*>(xr + c);
            ull xp0, xp1, xx0, xx1;
            asm("mov.b64 %0, {%1, %1};" : "=l"(xp0) : "f"(xv.x));
            asm("mov.b64 %0, {%1, %1};" : "=l"(xp1) : "f"(xv.y));
            asm("mul.rn.f32x2 %0, %1, %2;" : "=l"(xx0) : "l"(xp0), "l"(xp0));
            asm("mul.rn.f32x2 %0, %1, %2;" : "=l"(xx1) : "l"(xp1), "l"(xp1));
            #pragma unroll
            for (int i = 0; i < DS / 2; ++i) {
                asm("fma.rn.f32x2 %0, %1, %2, %3;"
                    : "=l"(s1p[i]) : "l"(s1p[i]), "l"(ap[i]), "l"(xp0));
                asm("fma.rn.f32x2 %0, %1, %2, %3;"
                    : "=l"(s2p[i]) : "l"(s2p[i]), "l"(ap[i]), "l"(xx0));
            }
            #pragma unroll
            for (int i = 0; i < DS / 2; ++i) {
                asm("fma.rn.f32x2 %0, %1, %2, %3;"
                    : "=l"(s1p[i]) : "l"(s1p[i]), "l"(ap[i]), "l"(xp1));
                asm("fma.rn.f32x2 %0, %1, %2, %3;"
                    : "=l"(s2p[i]) : "l"(s2p[i]), "l"(ap[i]), "l"(xx1));
            }
        }

        float S1[DS], S2[DS];
        #pragma unroll
        for (int i = 0; i < DS / 2; ++i) {
            asm("mov.b64 {%0, %1}, %2;" : "=f"(S1[2*i]), "=f"(S1[2*i+1]) : "l"(s1p[i]));
            asm("mov.b64 {%0, %1}, %2;" : "=f"(S2[2*i]), "=f"(S2[2*i+1]) : "l"(s2p[i]));
        }

        float accw = 0.f, accb = 0.f;
        #pragma unroll
        for (int i = 0; i < 4; ++i) {
            float4 t = cf[i];
            accw += t.x * S2[4*i] + t.y * S2[4*i+1] + t.z * S2[4*i+2] + t.w * S2[4*i+3];
        }
        #pragma unroll
        for (int i = 0; i < 4; ++i) {
            float4 t = cf[4 + i];
            accw += t.x * S1[4*i] + t.y * S1[4*i+1] + t.z * S1[4*i+2] + t.w * S1[4*i+3];
        }
        #pragma unroll
        for (int i = 0; i < 4; ++i) {
            float4 t = cf[8 + i];
            accb += t.x * S2[4*i] + t.y * S2[4*i+1] + t.z * S2[4*i+2] + t.w * S2[4*i+3];
        }
        #pragma unroll
        for (int i = 0; i < 4; ++i) {
            float4 t = cf[12 + i];
            accb += t.x * S1[4*i] + t.y * S1[4*i+1] + t.z * S1[4*i+2] + t.w * S1[4*i+3];
        }
        const float xlast = xr[N_BANDS - 1];
        sh_out[row][d] = xlast * (accw + k0w) + (accb + k0b);
    }
    __syncthreads();

    // ---- phase 4: out-proj + layernorm partials ----
    const float4* wrow = reinterpret_cast<const float4*>(Wo + d * DM);
    float zbuf[(MAXROWS + NGROUPS - 1) / NGROUPS];   // <= 4
    #pragma unroll 1
    for (int row = nl, j = 0; row < nrows; row += NGROUPS, ++j) {
        const float4* orow = reinterpret_cast<const float4*>(&sh_out[row][0]);
        float zz = bod;
        #pragma unroll
        for (int i = 0; i < DM / 4; ++i) {
            float4 w = wrow[i];
            float4 o4 = orow[i];
            zz += o4.x * w.x + o4.y * w.y + o4.z * w.z + o4.w * w.w;
        }
        zbuf[j] = zz;
        float sum = zz, sq = zz * zz;
        #pragma unroll
        for (int off = 16; off > 0; off >>= 1) {
            sum += __shfl_xor_sync(0xffffffffu, sum, off);
            sq  += __shfl_xor_sync(0xffffffffu, sq,  off);
        }
        if ((tid & 31) == 0) sh_part[row][(tid >> 5) & 1] = make_float2(sum, sq);
    }
    __syncthreads();

    #pragma unroll 1
    for (int row = nl, j = 0; row < nrows; row += NGROUPS, ++j) {
        float2 p0 = sh_part[row][0], p1 = sh_part[row][1];
        float mu  = (p0.x + p1.x) * (1.0f / DM);
        float var = (p0.y + p1.y) * (1.0f / DM) - mu * mu;
        float rn = rsqrtf(var + LN_EPS);
        out[(size_t)(row0 + row) * DM + d] = gd * (zbuf[j] - mu) * rn + btd;
    }
}

extern "C" void kernel_launch(void* const* d_in, const int* in_sizes, int n_in,
                              void* d_out, int out_size) {
    const float* x     = (const float*)d_in[0];
    const float* w_in  = (const float*)d_in[1];
    const float* b_in  = (const float*)d_in[2];
    const float* A_log = (const float*)d_in[3];
    const float* Wb    = (const float*)d_in[4];
    const float* Wc    = (const float*)d_in[5];
    const float* Dv    = (const float*)d_in[6];
    const float* Wo    = (const float*)d_in[7];
    const float* bo    = (const float*)d_in[8];
    const float* gm    = (const float*)d_in[9];
    const float* bt    = (const float*)d_in[10];
    float* out = (float*)d_out;

    int N = in_sizes[0] / N_BANDS;          // 4096
    int grid = 2 * 148;                     // exactly 2 blocks per SM
    // guard: rows per block must fit MAXROWS
    if ((N + grid - 1) / grid > MAXROWS) grid = (N + MAXROWS - 1) / MAXROWS;
    spectral_fused_kernel<<<grid, NTHREADS>>>(x, w_in, b_in, A_log, Wb, Wc, Dv,
                                              Wo, bo, gm, bt, out, N);
}